// round 13
// baseline (speedup 1.0000x reference)
#include <cuda_runtime.h>
#include <cstdint>

#define NC  5
#define TPB 256
#define MAXROWS 2097152

__device__ __forceinline__ float fast_ex2(float x) {
    float y; asm("ex2.approx.f32 %0, %1;" : "=f"(y) : "f"(x)); return y;
}
__device__ __forceinline__ float fast_lg2(float x) {
    float y; asm("lg2.approx.f32 %0, %1;" : "=f"(y) : "f"(x)); return y;
}
__device__ __forceinline__ float fast_rcp(float x) {
    float y; asm("rcp.approx.f32 %0, %1;" : "=f"(y) : "f"(x)); return y;
}
__device__ __forceinline__ float fast_rsq(float x) {
    float y; asm("rsqrt.approx.f32 %0, %1;" : "=f"(y) : "f"(x)); return y;
}

// h(t) = t*mu(t) - log2 Z(t) + C2 (log2 domain), C2=(ln5-eps)/ln2, increasing.
// h and the solver are scale-invariant in q, so normalized rows work.
#define C2CONST 2.1776498f     // (ln5 - 0.1)/ln2
#define LN2SQ   0.48045302f    // ln2^2
#define LN2CU   0.33302465f    // ln2^3
#define RLN2    1.44269504f    // 1/ln2
#define SQ2EPS  0.44721360f    // sqrt(2*eps)
#define CHI2MAX 0.10517092f    // e^eps - 1: chi2 <= this  =>  KL <= eps (Jensen)

__device__ int g_count;            // queue write cursor (0 at load & after reset)
__device__ int g_total;            // snapshot for pass 2
__device__ int g_done;             // blocks-finished counter
__device__ int g_queue[MAXROWS];   // 8 MB static scratch

__device__ __forceinline__ float solve_row(const float L[NC]) {
    float s1 = 0.f, s2 = 0.f, s3 = 0.f;
    #pragma unroll
    for (int j = 0; j < NC; j++) {
        float lj = L[j];
        s1 += lj; s2 = fmaf(lj, lj, s2); s3 = fmaf(lj * lj, lj, s3);
    }
    float m   = s1 * 0.2f;
    float e2  = s2 * 0.2f;
    float V   = fmaxf(LN2SQ * (e2 - m * m), 1e-9f);
    float m3  = LN2CU * fmaf(s3, 0.2f, fmaf(-3.f * m, e2, 2.f * m * m * m));
    float tl  = SQ2EPS * fast_rsq(V);
    float den = fmaxf(fmaf(0.6666667f * m3, tl, V), 1e-9f);
    float tc  = fminf(0.95f, fmaxf(SQ2EPS * fast_rsq(den), 1e-4f));

    float lo = 0.f, hi = 1.f;
    #pragma unroll
    for (int it = 0; it < 3; ++it) {
        float S = 0.f, A = 0.f, B = 0.f;
        #pragma unroll
        for (int j = 0; j < NC; j++) {
            float e  = fast_ex2(tc * L[j]);
            float el = e * L[j];
            S += e; A = fmaf(e, L[j], A); B = fmaf(el, L[j], B);
        }
        float r  = fast_rcp(S);
        float mu = A * r;
        float v  = fmaf(B, r, -(mu * mu));
        float h  = fmaf(tc, mu, C2CONST - fast_lg2(S));
        float hp = tc * v;
        bool pos = (h > 0.f);
        hi = pos ? tc : hi;
        lo = pos ? lo : tc;
        float tn = fmaf(-h * RLN2, fast_rcp(hp), tc);
        bool ok = (tn > lo) && (tn < hi);   // false also on NaN
        tc = ok ? tn : 0.5f * (lo + hi);
    }
    return tc;
}

// ---- Pass 1: FMA-only chi^2 screen, vec4 I/O, queue suspect rows ----
__global__ void __launch_bounds__(TPB) pass1_vec4(
    const float4* __restrict__ x4,
    const float*  __restrict__ W,
    const float*  __restrict__ b,
    float4* __restrict__ o4)
{
    __shared__ float sW[NC * NC];
    __shared__ float sb[NC];
    if (threadIdx.x < NC * NC) sW[threadIdx.x] = W[threadIdx.x];
    if (threadIdx.x < NC)      sb[threadIdx.x] = b[threadIdx.x];
    __syncthreads();

    size_t g = (size_t)blockIdx.x * TPB + threadIdx.x;
    const float4* xin = x4 + g * 5;

    float a[20];
    #pragma unroll
    for (int i = 0; i < 5; i++) {
        float4 v = xin[i];
        a[4*i+0] = v.x; a[4*i+1] = v.y; a[4*i+2] = v.z; a[4*i+3] = v.w;
    }

    int bad = 0;   // bitmask: row needs exact treatment in pass 2
    #pragma unroll
    for (int r = 0; r < 4; r++) {
        float q[NC];
        float s = 0.f, t2 = 0.f;
        #pragma unroll
        for (int j = 0; j < NC; j++) {
            float qq = sb[j];
            #pragma unroll
            for (int k = 0; k < NC; k++) qq = fmaf(a[r*NC + k], sW[j*NC + k], qq);
            q[j] = qq;
            s += qq;
            t2 = fmaf(qq, qq, t2);
        }
        float ir   = fast_rcp(s);
        float chi2 = fmaf(5.f * t2, ir * ir, -1.f);   // n*sum(q^2)/S^2 - 1
        if (chi2 > CHI2MAX) bad |= (1 << r);          // not provably feasible
        #pragma unroll
        for (int j = 0; j < NC; j++) a[r*NC + j] = q[j] * ir;   // p_hat
    }

    // Write normalized rows for ALL rows (exact for feasible; basis for pass 2).
    float4* oo = o4 + g * 5;
    #pragma unroll
    for (int i = 0; i < 5; i++)
        oo[i] = make_float4(a[4*i+0], a[4*i+1], a[4*i+2], a[4*i+3]);

    // Warp-aggregated queue push.
    int mycnt = __popc(bad);
    if (__ballot_sync(0xffffffffu, mycnt > 0)) {
        int lane = threadIdx.x & 31;
        int pre = mycnt;
        #pragma unroll
        for (int off = 1; off < 32; off <<= 1) {
            int v = __shfl_up_sync(0xffffffffu, pre, off);
            if (lane >= off) pre += v;
        }
        int total = __shfl_sync(0xffffffffu, pre, 31);
        int base = 0;
        if (lane == 31) base = atomicAdd(&g_count, total);
        base = __shfl_sync(0xffffffffu, base, 31);
        int pos = base + pre - mycnt;
        int bb = bad;
        while (bb) {
            int r = __ffs(bb) - 1;
            bb &= bb - 1;
            g_queue[pos++] = (int)(g * 4 + r);
        }
    }

    // Last block snapshots the count and resets state for the next replay.
    __syncthreads();
    __threadfence();
    if (threadIdx.x == 0) {
        int prev = atomicAdd(&g_done, 1);
        if (prev == (int)gridDim.x - 1) {
            g_total = g_count;
            g_count = 0;
            g_done  = 0;
            __threadfence();
        }
    }
}

// ---- Pass 2: exact check + solve on queued rows (reads normalized p_hat) ----
__global__ void __launch_bounds__(TPB) pass2_fix(float* __restrict__ out)
{
    int count = g_total;
    for (int i = blockIdx.x * blockDim.x + threadIdx.x;
         i < count;
         i += gridDim.x * blockDim.x)
    {
        int row = g_queue[i];
        float* po = out + (size_t)row * NC;
        float p[NC], L[NC];
        float A = 0.f;
        #pragma unroll
        for (int j = 0; j < NC; j++) {
            p[j] = po[j];
            L[j] = fast_lg2(p[j]);
            A = fmaf(p[j], L[j], A);
        }
        // Exact feasibility: sum(p_hat)=1, so h(1) = sum p log2 p + C2
        if (A + C2CONST > 0.f) {
            float t = solve_row(L);
            float e[NC], S = 0.f;
            #pragma unroll
            for (int j = 0; j < NC; j++) { e[j] = fast_ex2(t * L[j]); S += e[j]; }
            float r = fast_rcp(S);
            #pragma unroll
            for (int j = 0; j < NC; j++) po[j] = e[j] * r;
        }
        // else: row already holds the exact answer q/sum(q); leave it.
    }
}

// ---- Scalar fallback (any alignment / row count): self-contained ----
__global__ void __launch_bounds__(TPB) kl_proj_scalar(
    const float* __restrict__ x,
    const float* __restrict__ W,
    const float* __restrict__ b,
    float* __restrict__ out,
    int n)
{
    __shared__ float sW[NC * NC];
    __shared__ float sb[NC];
    if (threadIdx.x < NC * NC) sW[threadIdx.x] = W[threadIdx.x];
    if (threadIdx.x < NC)      sb[threadIdx.x] = b[threadIdx.x];
    __syncthreads();

    int row = blockIdx.x * blockDim.x + threadIdx.x;
    if (row >= n) return;

    float xv[NC];
    #pragma unroll
    for (int k = 0; k < NC; k++) xv[k] = x[row * NC + k];

    float q[NC];
    float s = 0.f, A = 0.f;
    #pragma unroll
    for (int j = 0; j < NC; j++) {
        float qq = sb[j];
        #pragma unroll
        for (int k = 0; k < NC; k++) qq = fmaf(xv[k], sW[j*NC + k], qq);
        q[j] = qq; s += qq;
        A = fmaf(qq, fast_lg2(qq), A);
    }
    float ir = fast_rcp(s);
    float h1 = A * ir - fast_lg2(s) + C2CONST;
    if (h1 > 0.f) {
        float L[NC];
        #pragma unroll
        for (int j = 0; j < NC; j++) L[j] = fast_lg2(q[j]);
        float t = solve_row(L);
        float S = 0.f;
        #pragma unroll
        for (int j = 0; j < NC; j++) { q[j] = fast_ex2(t * L[j]); S += q[j]; }
        ir = fast_rcp(S);
    }
    #pragma unroll
    for (int j = 0; j < NC; j++) out[row * NC + j] = q[j] * ir;
}

extern "C" void kernel_launch(void* const* d_in, const int* in_sizes, int n_in,
                              void* d_out, int out_size) {
    const float* x = (const float*)d_in[0];
    const float* W = (const float*)d_in[1];
    const float* b = (const float*)d_in[2];
    float* out = (float*)d_out;
    int n = in_sizes[0] / NC;

    bool aligned = ((((uintptr_t)x) | ((uintptr_t)out)) & 15u) == 0
                   && (n % (TPB * 4)) == 0 && n <= MAXROWS;
    if (aligned) {
        pass1_vec4<<<n / (TPB * 4), TPB>>>((const float4*)x, W, b, (float4*)out);
        pass2_fix<<<592, TPB>>>(out);
    } else {
        kl_proj_scalar<<<(n + TPB - 1) / TPB, TPB>>>(x, W, b, out, n);
    }
}

// round 14
// speedup vs baseline: 1.4504x; 1.4504x over previous
#include <cuda_runtime.h>
#include <cstdint>

#define NC  5
#define TPB 256

__device__ __forceinline__ float fast_ex2(float x) {
    float y; asm("ex2.approx.f32 %0, %1;" : "=f"(y) : "f"(x)); return y;
}
__device__ __forceinline__ float fast_lg2(float x) {
    float y; asm("lg2.approx.f32 %0, %1;" : "=f"(y) : "f"(x)); return y;
}
__device__ __forceinline__ float fast_rcp(float x) {
    float y; asm("rcp.approx.f32 %0, %1;" : "=f"(y) : "f"(x)); return y;
}
__device__ __forceinline__ float fast_rsq(float x) {
    float y; asm("rsqrt.approx.f32 %0, %1;" : "=f"(y) : "f"(x)); return y;
}

// h(t) = t*mu(t) - log2 Z(t) + C2 (log2 domain), C2=(ln5-eps)/ln2, increasing.
// p(t) = softmax(t * log2 q) (scale-invariant). Feasible (lam=0) iff h(1)<=0,
// then p = q / sum(q) exactly.
#define C2CONST 2.1776498f     // (ln5 - 0.1)/ln2
#define LN2SQ   0.48045302f    // ln2^2
#define LN2CU   0.33302465f    // ln2^3
#define RLN2    1.44269504f    // 1/ln2
#define SQ2EPS  0.44721360f    // sqrt(2*eps)

// Solve h(t)=0 on (0,1): cubic-Taylor init + 3 safeguarded Newton steps.
__device__ __forceinline__ float solve_row(const float L[NC]) {
    float s1 = 0.f, s2 = 0.f, s3 = 0.f;
    #pragma unroll
    for (int j = 0; j < NC; j++) {
        float lj = L[j];
        s1 += lj; s2 = fmaf(lj, lj, s2); s3 = fmaf(lj * lj, lj, s3);
    }
    float m   = s1 * 0.2f;
    float e2  = s2 * 0.2f;
    float V   = fmaxf(LN2SQ * (e2 - m * m), 1e-9f);
    float m3  = LN2CU * fmaf(s3, 0.2f, fmaf(-3.f * m, e2, 2.f * m * m * m));
    float tl  = SQ2EPS * fast_rsq(V);
    float den = fmaxf(fmaf(0.6666667f * m3, tl, V), 1e-9f);
    float tc  = fminf(0.95f, fmaxf(SQ2EPS * fast_rsq(den), 1e-4f));

    float lo = 0.f, hi = 1.f;
    #pragma unroll
    for (int it = 0; it < 3; ++it) {
        float S = 0.f, A = 0.f, B = 0.f;
        #pragma unroll
        for (int j = 0; j < NC; j++) {
            float e  = fast_ex2(tc * L[j]);
            float el = e * L[j];
            S += e; A = fmaf(e, L[j], A); B = fmaf(el, L[j], B);
        }
        float r  = fast_rcp(S);
        float mu = A * r;
        float v  = fmaf(B, r, -(mu * mu));
        float h  = fmaf(tc, mu, C2CONST - fast_lg2(S));
        float hp = tc * v;
        bool pos = (h > 0.f);
        hi = pos ? tc : hi;
        lo = pos ? lo : tc;
        float tn = fmaf(-h * RLN2, fast_rcp(hp), tc);
        bool ok = (tn > lo) && (tn < hi);   // false also on NaN
        tc = ok ? tn : 0.5f * (lo + hi);
    }
    return tc;
}

// ---------------- Main kernel: 2 rows/thread, float2 I/O ----------------
__global__ void __launch_bounds__(TPB) kl_proj_vec2(
    const float2* __restrict__ x2,
    const float*  __restrict__ W,
    const float*  __restrict__ b,
    float2* __restrict__ o2)
{
    __shared__ float sW[NC * NC];
    __shared__ float sb[NC];
    if (threadIdx.x < NC * NC) sW[threadIdx.x] = W[threadIdx.x];
    if (threadIdx.x < NC)      sb[threadIdx.x] = b[threadIdx.x];
    __syncthreads();

    size_t g = (size_t)blockIdx.x * TPB + threadIdx.x;   // rows 2g, 2g+1
    const float2* xin = x2 + g * 5;

    float a[10];
    #pragma unroll
    for (int i = 0; i < 5; i++) {
        float2 v = xin[i];
        a[2*i]   = v.x;
        a[2*i+1] = v.y;
    }

    // ---- Linear + feasibility for both rows (interleaved by scheduler) ----
    float inv[2];
    bool  feas[2];
    #pragma unroll
    for (int r = 0; r < 2; r++) {
        float q[NC];
        float s = 0.f, A = 0.f;
        #pragma unroll
        for (int j = 0; j < NC; j++) {
            float qq = sb[j];
            #pragma unroll
            for (int k = 0; k < NC; k++) qq = fmaf(a[r*NC + k], sW[j*NC + k], qq);
            q[j] = qq;
            s += qq;
            A = fmaf(qq, fast_lg2(qq), A);   // lg2 transient
        }
        float ir = fast_rcp(s);
        float h1 = A * ir - fast_lg2(s) + C2CONST;
        feas[r] = (h1 <= 0.f);
        inv[r]  = ir;
        #pragma unroll
        for (int j = 0; j < NC; j++) a[r*NC + j] = q[j];   // q overwrites x
    }

    // ---- Single vote; solver branch (skipped by ~50% of warps) ----
    if (!__all_sync(0xffffffffu, feas[0] && feas[1])) {
        #pragma unroll
        for (int r = 0; r < 2; r++) {
            if (!feas[r]) {
                float L[NC];
                #pragma unroll
                for (int j = 0; j < NC; j++) L[j] = fast_lg2(a[r*NC + j]);
                float t = solve_row(L);
                float S = 0.f;
                #pragma unroll
                for (int j = 0; j < NC; j++) {
                    float e = fast_ex2(t * L[j]);
                    a[r*NC + j] = e;
                    S += e;
                }
                inv[r] = fast_rcp(S);
            }
        }
    }

    // ---- Normalize + float2 stores ----
    #pragma unroll
    for (int j = 0; j < NC; j++) { a[j] *= inv[0]; a[NC + j] *= inv[1]; }

    float2* oo = o2 + g * 5;
    #pragma unroll
    for (int i = 0; i < 5; i++)
        oo[i] = make_float2(a[2*i], a[2*i+1]);
}

// ---------------- Scalar fallback (any alignment / row count) ----------------
__global__ void __launch_bounds__(TPB) kl_proj_scalar(
    const float* __restrict__ x,
    const float* __restrict__ W,
    const float* __restrict__ b,
    float* __restrict__ out,
    int n)
{
    __shared__ float sW[NC * NC];
    __shared__ float sb[NC];
    if (threadIdx.x < NC * NC) sW[threadIdx.x] = W[threadIdx.x];
    if (threadIdx.x < NC)      sb[threadIdx.x] = b[threadIdx.x];
    __syncthreads();

    int row = blockIdx.x * blockDim.x + threadIdx.x;
    if (row >= n) return;

    float xv[NC];
    #pragma unroll
    for (int k = 0; k < NC; k++) xv[k] = x[row * NC + k];

    float q[NC];
    float s = 0.f, A = 0.f;
    #pragma unroll
    for (int j = 0; j < NC; j++) {
        float qq = sb[j];
        #pragma unroll
        for (int k = 0; k < NC; k++) qq = fmaf(xv[k], sW[j*NC + k], qq);
        q[j] = qq; s += qq;
        A = fmaf(qq, fast_lg2(qq), A);
    }
    float ir = fast_rcp(s);
    float h1 = A * ir - fast_lg2(s) + C2CONST;
    bool feas = (h1 <= 0.f);

    if (!__all_sync(0xffffffffu, feas)) {
        if (!feas) {
            float L[NC];
            #pragma unroll
            for (int j = 0; j < NC; j++) L[j] = fast_lg2(q[j]);
            float t = solve_row(L);
            float S = 0.f;
            #pragma unroll
            for (int j = 0; j < NC; j++) { q[j] = fast_ex2(t * L[j]); S += q[j]; }
            ir = fast_rcp(S);
        }
    }
    #pragma unroll
    for (int j = 0; j < NC; j++) out[row * NC + j] = q[j] * ir;
}

extern "C" void kernel_launch(void* const* d_in, const int* in_sizes, int n_in,
                              void* d_out, int out_size) {
    const float* x = (const float*)d_in[0];
    const float* W = (const float*)d_in[1];
    const float* b = (const float*)d_in[2];
    float* out = (float*)d_out;
    int n = in_sizes[0] / NC;   // 2,097,152 rows

    bool ok = ((((uintptr_t)x) | ((uintptr_t)out)) & 7u) == 0
              && (n % (TPB * 2)) == 0;
    if (ok) {
        kl_proj_vec2<<<n / (TPB * 2), TPB>>>((const float2*)x, W, b, (float2*)out);
    } else {
        kl_proj_scalar<<<(n + TPB - 1) / TPB, TPB>>>(x, W, b, out, n);
    }
}

// round 15
// speedup vs baseline: 1.9594x; 1.3510x over previous
#include <cuda_runtime.h>
#include <cstdint>

#define NC  5
#define TPB 256
#define NBLK 1024   // 1024*256 threads * 8 rows = 2,097,152

__device__ __forceinline__ float fast_ex2(float x) {
    float y; asm("ex2.approx.f32 %0, %1;" : "=f"(y) : "f"(x)); return y;
}
__device__ __forceinline__ float fast_lg2(float x) {
    float y; asm("lg2.approx.f32 %0, %1;" : "=f"(y) : "f"(x)); return y;
}
__device__ __forceinline__ float fast_rcp(float x) {
    float y; asm("rcp.approx.f32 %0, %1;" : "=f"(y) : "f"(x)); return y;
}
__device__ __forceinline__ float fast_rsq(float x) {
    float y; asm("rsqrt.approx.f32 %0, %1;" : "=f"(y) : "f"(x)); return y;
}

// h(t) = t*mu(t) - log2 Z(t) + C2 (log2 domain), C2=(ln5-eps)/ln2, increasing.
// p(t) = softmax(t * log2 q). Feasible (lam=0) iff h(1) <= 0, then p = q/sum(q).
#define C2CONST 2.1776498f     // (ln5 - 0.1)/ln2
#define LN2SQ   0.48045302f    // ln2^2
#define LN2CU   0.33302465f    // ln2^3
#define RLN2    1.44269504f    // 1/ln2
#define SQ2EPS  0.44721360f    // sqrt(2*eps)

// Solve h(t)=0 on (0,1): cubic-Taylor init + 3 safeguarded Newton steps.
__device__ __forceinline__ float solve_row(const float L[NC]) {
    float s1 = 0.f, s2 = 0.f, s3 = 0.f;
    #pragma unroll
    for (int j = 0; j < NC; j++) {
        float lj = L[j];
        s1 += lj; s2 = fmaf(lj, lj, s2); s3 = fmaf(lj * lj, lj, s3);
    }
    float m   = s1 * 0.2f;
    float e2  = s2 * 0.2f;
    float V   = fmaxf(LN2SQ * (e2 - m * m), 1e-9f);
    float m3  = LN2CU * fmaf(s3, 0.2f, fmaf(-3.f * m, e2, 2.f * m * m * m));
    float tl  = SQ2EPS * fast_rsq(V);
    float den = fmaxf(fmaf(0.6666667f * m3, tl, V), 1e-9f);
    float tc  = fminf(0.95f, fmaxf(SQ2EPS * fast_rsq(den), 1e-4f));

    float lo = 0.f, hi = 1.f;
    #pragma unroll
    for (int it = 0; it < 3; ++it) {
        float S = 0.f, A = 0.f, B = 0.f;
        #pragma unroll
        for (int j = 0; j < NC; j++) {
            float e  = fast_ex2(tc * L[j]);
            float el = e * L[j];
            S += e; A = fmaf(e, L[j], A); B = fmaf(el, L[j], B);
        }
        float r  = fast_rcp(S);
        float mu = A * r;
        float v  = fmaf(B, r, -(mu * mu));
        float h  = fmaf(tc, mu, C2CONST - fast_lg2(S));
        float hp = tc * v;
        bool pos = (h > 0.f);
        hi = pos ? tc : hi;
        lo = pos ? lo : tc;
        float tn = fmaf(-h * RLN2, fast_rcp(hp), tc);
        bool ok = (tn > lo) && (tn < hi);   // false also on NaN
        tc = ok ? tn : 0.5f * (lo + hi);
    }
    return tc;
}

// Persistent grid-stride kernel with manual prefetch double-buffering:
// iteration i's compute overlaps iteration i+1's global loads.
__global__ void __launch_bounds__(TPB) kl_proj_persist(
    const float* __restrict__ x,
    const float* __restrict__ W,
    const float* __restrict__ b,
    float* __restrict__ out,
    int n)
{
    __shared__ float sW[NC * NC];
    __shared__ float sb[NC];
    if (threadIdx.x < NC * NC) sW[threadIdx.x] = W[threadIdx.x];
    if (threadIdx.x < NC)      sb[threadIdx.x] = b[threadIdx.x];
    __syncthreads();

    const int stride = gridDim.x * blockDim.x;
    int row = blockIdx.x * blockDim.x + threadIdx.x;

    float cur[NC];
    bool have = (row < n);
    if (have) {
        #pragma unroll
        for (int k = 0; k < NC; k++) cur[k] = x[(size_t)row * NC + k];
    }

    while (have) {
        // ---- Prefetch next row (overlaps with compute below) ----
        int  nrow  = row + stride;
        bool hnext = (nrow < n);
        float nxt[NC];
        if (hnext) {
            #pragma unroll
            for (int k = 0; k < NC; k++) nxt[k] = x[(size_t)nrow * NC + k];
        }

        // ---- Compute current row ----
        // q = x W^T + b, q in [0.1, 3.1] -> lg2/ex2 always safe, no max-shift.
        float q[NC];
        float s = 0.f, A = 0.f;
        #pragma unroll
        for (int j = 0; j < NC; j++) {
            float qq = sb[j];
            #pragma unroll
            for (int k = 0; k < NC; k++) qq = fmaf(cur[k], sW[j * NC + k], qq);
            q[j] = qq;
            s += qq;
            A = fmaf(qq, fast_lg2(qq), A);    // lg2 transient
        }
        float ir = fast_rcp(s);
        float h1 = A * ir - fast_lg2(s) + C2CONST;
        bool feas = (h1 <= 0.f);

        // Rare solver branch (warp-vote; ~28% of warp-iterations enter).
        if (!__all_sync(__activemask(), feas)) {
            if (!feas) {
                float L[NC];
                #pragma unroll
                for (int j = 0; j < NC; j++) L[j] = fast_lg2(q[j]);
                float t = solve_row(L);
                float S = 0.f;
                #pragma unroll
                for (int j = 0; j < NC; j++) { q[j] = fast_ex2(t * L[j]); S += q[j]; }
                ir = fast_rcp(S);
            }
        }

        // t = 1 shortcut is exact: p = q / sum(q). No ex2 on the common path.
        #pragma unroll
        for (int j = 0; j < NC; j++) out[(size_t)row * NC + j] = q[j] * ir;

        // ---- Rotate buffers ----
        row = nrow;
        have = hnext;
        #pragma unroll
        for (int k = 0; k < NC; k++) cur[k] = nxt[k];
    }
}

extern "C" void kernel_launch(void* const* d_in, const int* in_sizes, int n_in,
                              void* d_out, int out_size) {
    const float* x = (const float*)d_in[0];
    const float* W = (const float*)d_in[1];
    const float* b = (const float*)d_in[2];
    float* out = (float*)d_out;
    int n = in_sizes[0] / NC;   // 2,097,152 rows

    kl_proj_persist<<<NBLK, TPB>>>(x, W, b, out, n);
}